// round 1
// baseline (speedup 1.0000x reference)
#include <cuda_runtime.h>
#include <math.h>
#include <stddef.h>

// ---------------- problem constants ----------------
#define TOKS   8192          // B*N = 8*1024
#define CDIM   768
#define HID    384
#define NHEAD  12
#define HDIM   64
#define SEQ    1024
#define QKVC   2304          // 3*CDIM
#define NBH    96            // B*NHEAD

// ---------------- scratch (__device__ globals: allocation-guard safe) ---
__device__ float g_h[(size_t)TOKS * CDIM];          // LN output (reused)
__device__ float g_qkv[(size_t)TOKS * QKVC];        // qkv projection
__device__ float g_scores[(size_t)NBH * SEQ * SEQ]; // attention scores (403MB)
__device__ float g_att[(size_t)TOKS * CDIM];        // attention output (pre-proj)
__device__ float g_x1[(size_t)TOKS * CDIM];         // x after attn residual
__device__ float g_fc1[(size_t)TOKS * HID];         // gelu(fc1) output

// ---------------- LayerNorm: one block per row of 768 -------------------
__global__ void ln_kernel(const float* __restrict__ x, const float* __restrict__ w,
                          const float* __restrict__ b, float* __restrict__ out) {
    int row = blockIdx.x;
    const float* xr = x + (size_t)row * CDIM;
    float* orow = out + (size_t)row * CDIM;
    int t = threadIdx.x;
    float v0 = xr[t], v1 = xr[t + 256], v2 = xr[t + 512];
    float s = v0 + v1 + v2;
    float q = v0 * v0 + v1 * v1 + v2 * v2;
#pragma unroll
    for (int o = 16; o; o >>= 1) {
        s += __shfl_xor_sync(0xffffffffu, s, o);
        q += __shfl_xor_sync(0xffffffffu, q, o);
    }
    __shared__ float rs[8], rq[8];
    if ((t & 31) == 0) { rs[t >> 5] = s; rq[t >> 5] = q; }
    __syncthreads();
    if (t < 32) {
        float us = (t < 8) ? rs[t] : 0.f;
        float uq = (t < 8) ? rq[t] : 0.f;
#pragma unroll
        for (int o = 4; o; o >>= 1) {
            us += __shfl_xor_sync(0xffffffffu, us, o);
            uq += __shfl_xor_sync(0xffffffffu, uq, o);
        }
        if (t == 0) { rs[0] = us; rq[0] = uq; }
    }
    __syncthreads();
    float mu  = rs[0] * (1.f / CDIM);
    float var = rq[0] * (1.f / CDIM) - mu * mu;
    float inv = rsqrtf(var + 1e-5f);
    orow[t]       = (v0 - mu) * inv * w[t]       + b[t];
    orow[t + 256] = (v1 - mu) * inv * w[t + 256] + b[t + 256];
    orow[t + 512] = (v2 - mu) * inv * w[t + 512] + b[t + 512];
}

// ---------------- generic SGEMM, 64x64 tile, 4x4/thread, BK=16 ----------
// C[M,N] = A[M,K] @ B[K,N]  (+bias) (gelu) (+resid).  All dims % 64|16 == 0.
__global__ void sgemm_kernel(const float* __restrict__ A, const float* __restrict__ B,
                             float* __restrict__ C, int M, int N, int K,
                             const float* __restrict__ bias,
                             const float* __restrict__ resid, int gelu_flag) {
    __shared__ float As[16][68];
    __shared__ float Bs[16][64];
    int bm = blockIdx.y << 6, bn = blockIdx.x << 6;
    int tid = threadIdx.x;
    int tx = tid & 15, ty = tid >> 4;
    float acc[4][4] = {};
    int am = tid >> 2, ak = (tid & 3) << 2;
    const float* Aptr = A + (size_t)(bm + am) * K + ak;
    for (int k0 = 0; k0 < K; k0 += 16) {
        float4 a4 = *reinterpret_cast<const float4*>(Aptr + k0);
        As[ak + 0][am] = a4.x; As[ak + 1][am] = a4.y;
        As[ak + 2][am] = a4.z; As[ak + 3][am] = a4.w;
#pragma unroll
        for (int i = 0; i < 4; i++) {
            int idx = tid + (i << 8);
            int kk = idx >> 6, n = idx & 63;
            Bs[kk][n] = B[(size_t)(k0 + kk) * N + bn + n];
        }
        __syncthreads();
#pragma unroll
        for (int kk = 0; kk < 16; kk++) {
            float4 a = *reinterpret_cast<const float4*>(&As[kk][ty << 2]);
            float4 b = *reinterpret_cast<const float4*>(&Bs[kk][tx << 2]);
            float av[4] = {a.x, a.y, a.z, a.w};
            float bv[4] = {b.x, b.y, b.z, b.w};
#pragma unroll
            for (int i = 0; i < 4; i++)
#pragma unroll
                for (int j = 0; j < 4; j++)
                    acc[i][j] += av[i] * bv[j];
        }
        __syncthreads();
    }
#pragma unroll
    for (int i = 0; i < 4; i++) {
        int m = bm + (ty << 2) + i;
#pragma unroll
        for (int j = 0; j < 4; j++) {
            int n = bn + (tx << 2) + j;
            float v = acc[i][j];
            if (bias)  v += bias[n];
            if (gelu_flag) v = 0.5f * v * (1.f + erff(v * 0.70710678118654752f));
            if (resid) v += resid[(size_t)m * N + n];
            C[(size_t)m * N + n] = v;
        }
    }
}

// ---------------- QK^T: scores[bh,i,j] = 8 * sum_d q[i,d]*k[j,d] --------
__global__ void qk_kernel(const float* __restrict__ qkv, float* __restrict__ scores) {
    int bh = blockIdx.z;
    int b = bh / NHEAD, h = bh % NHEAD;
    const float* qb = qkv + (size_t)b * SEQ * QKVC + h * HDIM;
    const float* kb = qb + CDIM;  // k at column offset 768
    int bi = blockIdx.y << 6, bj = blockIdx.x << 6;
    __shared__ float Qs[64][68];
    __shared__ float Ks[64][68];
    int tid = threadIdx.x;
#pragma unroll
    for (int c = 0; c < 4; c++) {
        int idx = tid + (c << 8);
        int r = idx >> 4;            // 0..63
        int d0 = (idx & 15) << 2;    // 0..60
        float4 qv = *reinterpret_cast<const float4*>(qb + (size_t)(bi + r) * QKVC + d0);
        float4 kv = *reinterpret_cast<const float4*>(kb + (size_t)(bj + r) * QKVC + d0);
        Qs[d0 + 0][r] = qv.x; Qs[d0 + 1][r] = qv.y; Qs[d0 + 2][r] = qv.z; Qs[d0 + 3][r] = qv.w;
        Ks[d0 + 0][r] = kv.x; Ks[d0 + 1][r] = kv.y; Ks[d0 + 2][r] = kv.z; Ks[d0 + 3][r] = kv.w;
    }
    __syncthreads();
    int tx = tid & 15, ty = tid >> 4;
    float acc[4][4] = {};
#pragma unroll 8
    for (int d = 0; d < 64; d++) {
        float4 a = *reinterpret_cast<const float4*>(&Qs[d][ty << 2]);
        float4 bb = *reinterpret_cast<const float4*>(&Ks[d][tx << 2]);
        float av[4] = {a.x, a.y, a.z, a.w};
        float bv[4] = {bb.x, bb.y, bb.z, bb.w};
#pragma unroll
        for (int i = 0; i < 4; i++)
#pragma unroll
            for (int j = 0; j < 4; j++)
                acc[i][j] += av[i] * bv[j];
    }
    float* srow = scores + ((size_t)bh << 20);
#pragma unroll
    for (int i = 0; i < 4; i++)
#pragma unroll
        for (int j = 0; j < 4; j++)
            srow[(size_t)(bi + (ty << 2) + i) * SEQ + bj + (tx << 2) + j] = acc[i][j] * 8.0f;
}

// ---------------- softmax over rows of 1024 ------------------------------
__global__ void softmax_kernel(float* __restrict__ scores) {
    size_t row = blockIdx.x;
    float4* r = reinterpret_cast<float4*>(scores + row * SEQ);
    int t = threadIdx.x;
    float4 v = r[t];
    float m = fmaxf(fmaxf(v.x, v.y), fmaxf(v.z, v.w));
#pragma unroll
    for (int o = 16; o; o >>= 1) m = fmaxf(m, __shfl_xor_sync(0xffffffffu, m, o));
    __shared__ float red[8];
    if ((t & 31) == 0) red[t >> 5] = m;
    __syncthreads();
    if (t < 32) {
        float u = (t < 8) ? red[t] : -3.4e38f;
#pragma unroll
        for (int o = 4; o; o >>= 1) u = fmaxf(u, __shfl_xor_sync(0xffffffffu, u, o));
        if (t == 0) red[0] = u;
    }
    __syncthreads();
    float M = red[0];
    __syncthreads();
    v.x = __expf(v.x - M); v.y = __expf(v.y - M);
    v.z = __expf(v.z - M); v.w = __expf(v.w - M);
    float s = v.x + v.y + v.z + v.w;
#pragma unroll
    for (int o = 16; o; o >>= 1) s += __shfl_xor_sync(0xffffffffu, s, o);
    if ((t & 31) == 0) red[t >> 5] = s;
    __syncthreads();
    if (t < 32) {
        float u = (t < 8) ? red[t] : 0.f;
#pragma unroll
        for (int o = 4; o; o >>= 1) u += __shfl_xor_sync(0xffffffffu, u, o);
        if (t == 0) red[0] = u;
    }
    __syncthreads();
    float inv = 1.f / red[0];
    v.x *= inv; v.y *= inv; v.z *= inv; v.w *= inv;
    r[t] = v;
}

// ---------------- attn @ V: out[bh,i,d] written into [B,N,C] layout ------
__global__ void av_kernel(const float* __restrict__ scores, const float* __restrict__ qkv,
                          float* __restrict__ att) {
    int bh = blockIdx.z;
    int b = bh / NHEAD, h = bh % NHEAD;
    int bi = blockIdx.y << 6;
    const float* S = scores + ((size_t)bh << 20) + (size_t)bi * SEQ;
    const float* vb = qkv + (size_t)b * SEQ * QKVC + 2 * CDIM + h * HDIM;
    __shared__ float Ss[16][68];
    __shared__ float Vs[16][64];
    int tid = threadIdx.x, tx = tid & 15, ty = tid >> 4;
    float acc[4][4] = {};
    int si = tid >> 2, sj = (tid & 3) << 2;
    for (int j0 = 0; j0 < SEQ; j0 += 16) {
        float4 sv = *reinterpret_cast<const float4*>(S + (size_t)si * SEQ + j0 + sj);
        Ss[sj + 0][si] = sv.x; Ss[sj + 1][si] = sv.y;
        Ss[sj + 2][si] = sv.z; Ss[sj + 3][si] = sv.w;
#pragma unroll
        for (int c = 0; c < 4; c++) {
            int idx = tid + (c << 8);
            int j = idx >> 6, d = idx & 63;
            Vs[j][d] = vb[(size_t)(j0 + j) * QKVC + d];
        }
        __syncthreads();
#pragma unroll
        for (int kk = 0; kk < 16; kk++) {
            float4 a = *reinterpret_cast<const float4*>(&Ss[kk][ty << 2]);
            float4 bb = *reinterpret_cast<const float4*>(&Vs[kk][tx << 2]);
            float av[4] = {a.x, a.y, a.z, a.w};
            float bv[4] = {bb.x, bb.y, bb.z, bb.w};
#pragma unroll
            for (int i = 0; i < 4; i++)
#pragma unroll
                for (int j = 0; j < 4; j++)
                    acc[i][j] += av[i] * bv[j];
        }
        __syncthreads();
    }
#pragma unroll
    for (int i = 0; i < 4; i++)
#pragma unroll
        for (int j = 0; j < 4; j++)
            att[((size_t)b * SEQ + bi + (ty << 2) + i) * CDIM + h * HDIM + (tx << 2) + j] =
                acc[i][j];
}

// ---------------- launch --------------------------------------------------
extern "C" void kernel_launch(void* const* d_in, const int* in_sizes, int n_in,
                              void* d_out, int out_size) {
    const float* x     = (const float*)d_in[0];
    const float* ln1w  = (const float*)d_in[1];
    const float* ln1b  = (const float*)d_in[2];
    const float* ln2w  = (const float*)d_in[3];
    const float* ln2b  = (const float*)d_in[4];
    const float* wqkv  = (const float*)d_in[5];
    const float* wproj = (const float*)d_in[6];
    const float* wfc1  = (const float*)d_in[7];
    const float* bfc1  = (const float*)d_in[8];
    const float* wfc2  = (const float*)d_in[9];
    const float* bfc2  = (const float*)d_in[10];
    float* out = (float*)d_out;

    float *p_h, *p_qkv, *p_scores, *p_att, *p_x1, *p_fc1;
    cudaGetSymbolAddress((void**)&p_h, g_h);
    cudaGetSymbolAddress((void**)&p_qkv, g_qkv);
    cudaGetSymbolAddress((void**)&p_scores, g_scores);
    cudaGetSymbolAddress((void**)&p_att, g_att);
    cudaGetSymbolAddress((void**)&p_x1, g_x1);
    cudaGetSymbolAddress((void**)&p_fc1, g_fc1);

    // 1) h = LN1(x)
    ln_kernel<<<TOKS, 256>>>(x, ln1w, ln1b, p_h);
    // 2) qkv = h @ w_qkv              [8192,2304]
    sgemm_kernel<<<dim3(QKVC / 64, TOKS / 64), 256>>>(p_h, wqkv, p_qkv,
                                                      TOKS, QKVC, CDIM,
                                                      nullptr, nullptr, 0);
    // 3) scores = 8 * Q @ K^T         per (b,h)
    qk_kernel<<<dim3(16, 16, NBH), 256>>>(p_qkv, p_scores);
    // 4) softmax rows
    softmax_kernel<<<NBH * SEQ, 256>>>(p_scores);
    // 5) att = softmax @ V  (back into [B,N,C])
    av_kernel<<<dim3(1, 16, NBH), 256>>>(p_scores, p_qkv, p_att);
    // 6) x1 = x + att @ w_proj
    sgemm_kernel<<<dim3(CDIM / 64, TOKS / 64), 256>>>(p_att, wproj, p_x1,
                                                      TOKS, CDIM, CDIM,
                                                      nullptr, x, 0);
    // 7) h = LN2(x1)
    ln_kernel<<<TOKS, 256>>>(p_x1, ln2w, ln2b, p_h);
    // 8) fc1 = gelu(h @ w_fc1 + b_fc1)
    sgemm_kernel<<<dim3(HID / 64, TOKS / 64), 256>>>(p_h, wfc1, p_fc1,
                                                     TOKS, HID, CDIM,
                                                     bfc1, nullptr, 1);
    // 9) out = x1 + fc1 @ w_fc2 + b_fc2
    sgemm_kernel<<<dim3(CDIM / 64, TOKS / 64), 256>>>(p_fc1, wfc2, out,
                                                      TOKS, CDIM, HID,
                                                      bfc2, p_x1, 0);
}

// round 2
// speedup vs baseline: 1.2248x; 1.2248x over previous
#include <cuda_runtime.h>
#include <math.h>
#include <stddef.h>

// ---------------- problem constants ----------------
#define TOKS   8192          // B*N = 8*1024
#define CDIM   768
#define HID    384
#define NHEAD  12
#define HDIM   64
#define SEQ    1024
#define QKVC   2304          // 3*CDIM
#define NBH    96            // B*NHEAD

// ---------------- scratch (__device__ globals) ---------------------------
__device__ float g_h[(size_t)TOKS * CDIM];
__device__ float g_qkv[(size_t)TOKS * QKVC];
__device__ float g_att[(size_t)TOKS * CDIM];
__device__ float g_x1[(size_t)TOKS * CDIM];
__device__ float g_fc1[(size_t)TOKS * HID];

// ---------------- packed f32x2 helpers -----------------------------------
typedef unsigned long long u64;

__device__ __forceinline__ void ffma2(u64 &d, u64 a, u64 b) {
    asm("fma.rn.f32x2 %0, %1, %2, %0;" : "+l"(d) : "l"(a), "l"(b));
}
__device__ __forceinline__ u64 dup2(float x) {
    u64 r; asm("mov.b64 %0, {%1, %1};" : "=l"(r) : "f"(x)); return r;
}
__device__ __forceinline__ u64 pack2(float lo, float hi) {
    u64 r; asm("mov.b64 %0, {%1, %2};" : "=l"(r) : "f"(lo), "f"(hi)); return r;
}
__device__ __forceinline__ void unpack2(u64 v, float &lo, float &hi) {
    asm("mov.b64 {%0, %1}, %2;" : "=f"(lo), "=f"(hi) : "l"(v));
}
__device__ __forceinline__ void mul2(u64 &d, u64 a) {
    asm("mul.rn.f32x2 %0, %0, %1;" : "+l"(d) : "l"(a));
}

// ---------------- LayerNorm: one block per row of 768 --------------------
__global__ void ln_kernel(const float* __restrict__ x, const float* __restrict__ w,
                          const float* __restrict__ b, float* __restrict__ out) {
    int row = blockIdx.x;
    const float* xr = x + (size_t)row * CDIM;
    float* orow = out + (size_t)row * CDIM;
    int t = threadIdx.x;
    float v0 = xr[t], v1 = xr[t + 256], v2 = xr[t + 512];
    float s = v0 + v1 + v2;
    float q = v0 * v0 + v1 * v1 + v2 * v2;
#pragma unroll
    for (int o = 16; o; o >>= 1) {
        s += __shfl_xor_sync(0xffffffffu, s, o);
        q += __shfl_xor_sync(0xffffffffu, q, o);
    }
    __shared__ float rs[8], rq[8];
    if ((t & 31) == 0) { rs[t >> 5] = s; rq[t >> 5] = q; }
    __syncthreads();
    if (t < 32) {
        float us = (t < 8) ? rs[t] : 0.f;
        float uq = (t < 8) ? rq[t] : 0.f;
#pragma unroll
        for (int o = 4; o; o >>= 1) {
            us += __shfl_xor_sync(0xffffffffu, us, o);
            uq += __shfl_xor_sync(0xffffffffu, uq, o);
        }
        if (t == 0) { rs[0] = us; rq[0] = uq; }
    }
    __syncthreads();
    float mu  = rs[0] * (1.f / CDIM);
    float var = rq[0] * (1.f / CDIM) - mu * mu;
    float inv = rsqrtf(var + 1e-5f);
    orow[t]       = (v0 - mu) * inv * w[t]       + b[t];
    orow[t + 256] = (v1 - mu) * inv * w[t + 256] + b[t + 256];
    orow[t + 512] = (v2 - mu) * inv * w[t + 512] + b[t + 512];
}

// ---------------- SGEMM 128x128x16, 8x8/thread, f32x2, double-buffered ---
// C[M,N] = A[M,K] @ B[K,N]  (+bias) (gelu) (+resid).  M%128==N%128==K%16==0.
__global__ void __launch_bounds__(256, 2)
sgemm128(const float* __restrict__ A, const float* __restrict__ B,
         float* __restrict__ C, int M, int N, int K,
         const float* __restrict__ bias, const float* __restrict__ resid,
         int gelu_flag) {
    __shared__ float As[2][16][132];   // transposed A tile, padded
    __shared__ float Bs[2][16][128];
    const int tid = threadIdx.x;
    const int tx = tid & 15, ty = tid >> 4;
    const int bm = blockIdx.y << 7, bn = blockIdx.x << 7;

    const int ar = tid >> 2, ak = (tid & 3) << 2;        // A: rows ar, ar+64
    const int bk = tid >> 5, bn4 = (tid & 31) << 2;      // B: rows bk, bk+8

    u64 acc[8][4];
#pragma unroll
    for (int i = 0; i < 8; i++)
#pragma unroll
        for (int j = 0; j < 4; j++) acc[i][j] = 0ULL;

    const float* Abase = A + (size_t)bm * K + ak;
    const float* Bbase = B + bn + bn4;

    // prologue: tile 0 -> buf 0
    {
        float4 a0 = *(const float4*)(Abase + (size_t)ar * K);
        float4 a1 = *(const float4*)(Abase + (size_t)(ar + 64) * K);
        As[0][ak + 0][ar] = a0.x; As[0][ak + 1][ar] = a0.y;
        As[0][ak + 2][ar] = a0.z; As[0][ak + 3][ar] = a0.w;
        As[0][ak + 0][ar + 64] = a1.x; As[0][ak + 1][ar + 64] = a1.y;
        As[0][ak + 2][ar + 64] = a1.z; As[0][ak + 3][ar + 64] = a1.w;
        float4 b0 = *(const float4*)(Bbase + (size_t)bk * N);
        float4 b1 = *(const float4*)(Bbase + (size_t)(bk + 8) * N);
        *(float4*)&Bs[0][bk][bn4] = b0;
        *(float4*)&Bs[0][bk + 8][bn4] = b1;
    }
    __syncthreads();

    int buf = 0;
    for (int k0 = 0; k0 < K; k0 += 16) {
        float4 pa0, pa1, pb0, pb1;
        bool more = (k0 + 16) < K;
        if (more) {
            const float* An = Abase + k0 + 16;
            pa0 = *(const float4*)(An + (size_t)ar * K);
            pa1 = *(const float4*)(An + (size_t)(ar + 64) * K);
            const float* Bn = Bbase + (size_t)(k0 + 16) * N;
            pb0 = *(const float4*)(Bn + (size_t)bk * N);
            pb1 = *(const float4*)(Bn + (size_t)(bk + 8) * N);
        }
#pragma unroll
        for (int kk = 0; kk < 16; kk++) {
            float4 af0 = *(const float4*)&As[buf][kk][ty << 3];
            float4 af1 = *(const float4*)&As[buf][kk][(ty << 3) + 4];
            ulonglong2 bq0 = *(const ulonglong2*)&Bs[buf][kk][tx << 3];
            ulonglong2 bq1 = *(const ulonglong2*)&Bs[buf][kk][(tx << 3) + 4];
            u64 ad[8] = {dup2(af0.x), dup2(af0.y), dup2(af0.z), dup2(af0.w),
                         dup2(af1.x), dup2(af1.y), dup2(af1.z), dup2(af1.w)};
            u64 bb[4] = {bq0.x, bq0.y, bq1.x, bq1.y};
#pragma unroll
            for (int i = 0; i < 8; i++)
#pragma unroll
                for (int j = 0; j < 4; j++) ffma2(acc[i][j], ad[i], bb[j]);
        }
        if (more) {
            int nb = buf ^ 1;
            As[nb][ak + 0][ar] = pa0.x; As[nb][ak + 1][ar] = pa0.y;
            As[nb][ak + 2][ar] = pa0.z; As[nb][ak + 3][ar] = pa0.w;
            As[nb][ak + 0][ar + 64] = pa1.x; As[nb][ak + 1][ar + 64] = pa1.y;
            As[nb][ak + 2][ar + 64] = pa1.z; As[nb][ak + 3][ar + 64] = pa1.w;
            *(float4*)&Bs[nb][bk][bn4] = pb0;
            *(float4*)&Bs[nb][bk + 8][bn4] = pb1;
        }
        __syncthreads();
        buf ^= 1;
    }

    // epilogue
    const int m0 = bm + (ty << 3);
    const int n0 = bn + (tx << 3);
#pragma unroll
    for (int i = 0; i < 8; i++) {
        float* Crow = C + (size_t)(m0 + i) * N + n0;
        const float* Rrow = resid ? resid + (size_t)(m0 + i) * N + n0 : (const float*)0;
#pragma unroll
        for (int jp = 0; jp < 4; jp++) {
            float lo, hi;
            unpack2(acc[i][jp], lo, hi);
            int n = jp << 1;
            if (bias) { lo += bias[n0 + n]; hi += bias[n0 + n + 1]; }
            if (gelu_flag) {
                lo = 0.5f * lo * (1.f + erff(lo * 0.70710678118654752f));
                hi = 0.5f * hi * (1.f + erff(hi * 0.70710678118654752f));
            }
            if (Rrow) { lo += Rrow[n]; hi += Rrow[n + 1]; }
            Crow[n] = lo; Crow[n + 1] = hi;
        }
    }
}

// ---------------- fused flash attention ----------------------------------
// One CTA: 128 q rows of one (b,h). KV tiles of 128. Online softmax.
// scores = 8 * Q K^T (scale folded into Q load).
__global__ void __launch_bounds__(256, 1)
flash_kernel(const float* __restrict__ qkv, float* __restrict__ att) {
    extern __shared__ float sm[];
    float* Qs = sm;                    // [64][132]  (d-major, transposed)
    float* Ks = Qs + 64 * 132;         // [64][132]
    float* Vs = Ks + 64 * 132;         // [128][68]
    float* Ps = Vs + 128 * 68;         // [128][128] swizzled

    const int tid = threadIdx.x;
    const int tx = tid & 15, ty = tid >> 4;
    const int qb = blockIdx.x << 7;
    const int bh = blockIdx.y;
    const int b = bh / NHEAD, h = bh % NHEAD;
    const float* qptr = qkv + (size_t)b * SEQ * QKVC + h * HDIM;
    const float* kptr = qptr + CDIM;
    const float* vptr = qptr + 2 * CDIM;

    // load Q (x8 scale) transposed: Qs[d][r]
#pragma unroll
    for (int c = 0; c < 8; c++) {
        int idx = tid + (c << 8);
        int r = idx >> 4;
        int d4 = (idx & 15) << 2;
        float4 v = *(const float4*)(qptr + (size_t)(qb + r) * QKVC + d4);
        Qs[(d4 + 0) * 132 + r] = v.x * 8.0f;
        Qs[(d4 + 1) * 132 + r] = v.y * 8.0f;
        Qs[(d4 + 2) * 132 + r] = v.z * 8.0f;
        Qs[(d4 + 3) * 132 + r] = v.w * 8.0f;
    }

    float m_i[8], l_i[8];
#pragma unroll
    for (int i = 0; i < 8; i++) { m_i[i] = -3.4e38f; l_i[i] = 0.f; }
    u64 Oa[4][4];                      // rows paired (2p,2p+1), cols d=4tx+e
#pragma unroll
    for (int p = 0; p < 4; p++)
#pragma unroll
        for (int e = 0; e < 4; e++) Oa[p][e] = 0ULL;

    const int sw = tx & 7;

    for (int n0 = 0; n0 < SEQ; n0 += 128) {
        __syncthreads();   // prior O-GEMM done before overwriting K/V
        // load K transposed, V natural
#pragma unroll
        for (int c = 0; c < 8; c++) {
            int idx = tid + (c << 8);
            int r = idx >> 4;
            int d4 = (idx & 15) << 2;
            float4 kv = *(const float4*)(kptr + (size_t)(n0 + r) * QKVC + d4);
            Ks[(d4 + 0) * 132 + r] = kv.x;
            Ks[(d4 + 1) * 132 + r] = kv.y;
            Ks[(d4 + 2) * 132 + r] = kv.z;
            Ks[(d4 + 3) * 132 + r] = kv.w;
            float4 vv = *(const float4*)(vptr + (size_t)(n0 + r) * QKVC + d4);
            *(float4*)&Vs[r * 68 + d4] = vv;
        }
        __syncthreads();

        // ---- S = Q^T(scaled) @ K : 128x128, this thread 8 rows x 8 cols
        u64 sacc[8][4];
#pragma unroll
        for (int i = 0; i < 8; i++)
#pragma unroll
            for (int j = 0; j < 4; j++) sacc[i][j] = 0ULL;
#pragma unroll 8
        for (int kk = 0; kk < 64; kk++) {
            float4 a0 = *(const float4*)&Qs[kk * 132 + (ty << 3)];
            float4 a1 = *(const float4*)&Qs[kk * 132 + (ty << 3) + 4];
            ulonglong2 b0 = *(const ulonglong2*)&Ks[kk * 132 + (tx << 3)];
            ulonglong2 b1 = *(const ulonglong2*)&Ks[kk * 132 + (tx << 3) + 4];
            u64 ad[8] = {dup2(a0.x), dup2(a0.y), dup2(a0.z), dup2(a0.w),
                         dup2(a1.x), dup2(a1.y), dup2(a1.z), dup2(a1.w)};
            u64 bb[4] = {b0.x, b0.y, b1.x, b1.y};
#pragma unroll
            for (int i = 0; i < 8; i++)
#pragma unroll
                for (int j = 0; j < 4; j++) ffma2(sacc[i][j], ad[i], bb[j]);
        }

        // ---- online softmax (rows split across the 16 tx lanes)
        float p[8][8];
#pragma unroll
        for (int i = 0; i < 8; i++)
#pragma unroll
            for (int jp = 0; jp < 4; jp++)
                unpack2(sacc[i][jp], p[i][2 * jp], p[i][2 * jp + 1]);

        float c8[8];
#pragma unroll
        for (int i = 0; i < 8; i++) {
            float mx = p[i][0];
#pragma unroll
            for (int j = 1; j < 8; j++) mx = fmaxf(mx, p[i][j]);
#pragma unroll
            for (int o = 8; o; o >>= 1) mx = fmaxf(mx, __shfl_xor_sync(0xffffffffu, mx, o));
            float mnew = fmaxf(m_i[i], mx);
            c8[i] = __expf(m_i[i] - mnew);
            m_i[i] = mnew;
            float rs = 0.f;
#pragma unroll
            for (int j = 0; j < 8; j++) { p[i][j] = __expf(p[i][j] - mnew); rs += p[i][j]; }
#pragma unroll
            for (int o = 8; o; o >>= 1) rs += __shfl_xor_sync(0xffffffffu, rs, o);
            l_i[i] = l_i[i] * c8[i] + rs;
        }
#pragma unroll
        for (int p2 = 0; p2 < 4; p2++) {
            u64 cp = pack2(c8[2 * p2], c8[2 * p2 + 1]);
#pragma unroll
            for (int e = 0; e < 4; e++) mul2(Oa[p2][e], cp);
        }

        // ---- store P transposed + swizzled: Ps[j][i], phys i4' = i4 ^ ((j>>3)&7)
#pragma unroll
        for (int jj = 0; jj < 8; jj++) {
            float* prow = Ps + ((tx << 3) + jj) * 128;
            *(float4*)&prow[(((ty << 1) + 0) ^ sw) << 2] =
                make_float4(p[0][jj], p[1][jj], p[2][jj], p[3][jj]);
            *(float4*)&prow[(((ty << 1) + 1) ^ sw) << 2] =
                make_float4(p[4][jj], p[5][jj], p[6][jj], p[7][jj]);
        }
        __syncthreads();

        // ---- O += P @ V : rows paired along i (natural pairs from Ps)
#pragma unroll 8
        for (int kk = 0; kk < 128; kk++) {
            int swk = (kk >> 3) & 7;
            const float* prow = Ps + kk * 128;
            ulonglong2 ap0 = *(const ulonglong2*)&prow[(((ty << 1) + 0) ^ swk) << 2];
            ulonglong2 ap1 = *(const ulonglong2*)&prow[(((ty << 1) + 1) ^ swk) << 2];
            float4 vf = *(const float4*)&Vs[kk * 68 + (tx << 2)];
            u64 vd[4] = {dup2(vf.x), dup2(vf.y), dup2(vf.z), dup2(vf.w)};
            u64 aa[4] = {ap0.x, ap0.y, ap1.x, ap1.y};
#pragma unroll
            for (int p2 = 0; p2 < 4; p2++)
#pragma unroll
                for (int e = 0; e < 4; e++) ffma2(Oa[p2][e], aa[p2], vd[e]);
        }
    }

    // ---- epilogue: O / l -> att in [B,N,C] layout
#pragma unroll
    for (int p2 = 0; p2 < 4; p2++) {
        int i0 = (ty << 3) + 2 * p2;
        float inv0 = 1.f / l_i[2 * p2];
        float inv1 = 1.f / l_i[2 * p2 + 1];
        float* o0 = att + ((size_t)(b * SEQ + qb + i0)) * CDIM + h * HDIM + (tx << 2);
        float* o1 = o0 + CDIM;
        float v0[4], v1[4];
#pragma unroll
        for (int e = 0; e < 4; e++) {
            float lo, hi;
            unpack2(Oa[p2][e], lo, hi);
            v0[e] = lo * inv0;
            v1[e] = hi * inv1;
        }
        *(float4*)o0 = make_float4(v0[0], v0[1], v0[2], v0[3]);
        *(float4*)o1 = make_float4(v1[0], v1[1], v1[2], v1[3]);
    }
}

// ---------------- launch --------------------------------------------------
extern "C" void kernel_launch(void* const* d_in, const int* in_sizes, int n_in,
                              void* d_out, int out_size) {
    const float* x     = (const float*)d_in[0];
    const float* ln1w  = (const float*)d_in[1];
    const float* ln1b  = (const float*)d_in[2];
    const float* ln2w  = (const float*)d_in[3];
    const float* ln2b  = (const float*)d_in[4];
    const float* wqkv  = (const float*)d_in[5];
    const float* wproj = (const float*)d_in[6];
    const float* wfc1  = (const float*)d_in[7];
    const float* bfc1  = (const float*)d_in[8];
    const float* wfc2  = (const float*)d_in[9];
    const float* bfc2  = (const float*)d_in[10];
    float* out = (float*)d_out;

    float *p_h, *p_qkv, *p_att, *p_x1, *p_fc1;
    cudaGetSymbolAddress((void**)&p_h, g_h);
    cudaGetSymbolAddress((void**)&p_qkv, g_qkv);
    cudaGetSymbolAddress((void**)&p_att, g_att);
    cudaGetSymbolAddress((void**)&p_x1, g_x1);
    cudaGetSymbolAddress((void**)&p_fc1, g_fc1);

    static const int FLASH_SMEM = (64 * 132 + 64 * 132 + 128 * 68 + 128 * 128) * 4;
    cudaFuncSetAttribute(flash_kernel, cudaFuncAttributeMaxDynamicSharedMemorySize,
                         FLASH_SMEM);

    // 1) h = LN1(x)
    ln_kernel<<<TOKS, 256>>>(x, ln1w, ln1b, p_h);
    // 2) qkv = h @ w_qkv
    sgemm128<<<dim3(QKVC / 128, TOKS / 128), 256>>>(p_h, wqkv, p_qkv,
                                                    TOKS, QKVC, CDIM,
                                                    nullptr, nullptr, 0);
    // 3-5) fused attention
    flash_kernel<<<dim3(SEQ / 128, NBH), 256, FLASH_SMEM>>>(p_qkv, p_att);
    // 6) x1 = x + att @ w_proj
    sgemm128<<<dim3(CDIM / 128, TOKS / 128), 256>>>(p_att, wproj, p_x1,
                                                    TOKS, CDIM, CDIM,
                                                    nullptr, x, 0);
    // 7) h = LN2(x1)
    ln_kernel<<<TOKS, 256>>>(p_x1, ln2w, ln2b, p_h);
    // 8) fc1 = gelu(h @ w_fc1 + b_fc1)
    sgemm128<<<dim3(HID / 128, TOKS / 128), 256>>>(p_h, wfc1, p_fc1,
                                                   TOKS, HID, CDIM,
                                                   bfc1, nullptr, 1);
    // 9) out = x1 + fc1 @ w_fc2 + b_fc2
    sgemm128<<<dim3(CDIM / 128, TOKS / 128), 256>>>(p_fc1, wfc2, out,
                                                    TOKS, CDIM, HID,
                                                    bfc2, p_x1, 0);
}

// round 4
// speedup vs baseline: 2.4196x; 1.9755x over previous
#include <cuda_runtime.h>
#include <math.h>
#include <stddef.h>
#include <stdint.h>

// ---------------- problem constants ----------------
#define TOKS   8192
#define CDIM   768
#define HID    384
#define NHEAD  12
#define HDIM   64
#define SEQ    1024
#define QKVC   2304
#define NBH    96

// ---------------- scratch ---------------------------
__device__ float g_h[(size_t)TOKS * CDIM];
__device__ float g_qkv[(size_t)TOKS * QKVC];
__device__ float g_att[(size_t)TOKS * CDIM];
__device__ float g_x1[(size_t)TOKS * CDIM];
__device__ float g_fc1[(size_t)TOKS * HID];
__device__ float g_wqkv_t[(size_t)QKVC * CDIM];
__device__ float g_wproj_t[(size_t)CDIM * CDIM];
__device__ float g_wfc1_t[(size_t)HID * CDIM];
__device__ float g_wfc2_t[(size_t)CDIM * HID];

typedef unsigned long long u64;

// ---------------- helpers -----------------------
__device__ __forceinline__ uint32_t smem_u32(const void* p) {
    uint32_t a;
    asm("{ .reg .u64 t; cvta.to.shared.u64 t, %1; cvt.u32.u64 %0, t; }" : "=r"(a) : "l"(p));
    return a;
}
__device__ __forceinline__ void cp_async16(uint32_t dst, const void* src) {
    asm volatile("cp.async.cg.shared.global [%0], [%1], 16;" :: "r"(dst), "l"(src));
}
#define CP_COMMIT() asm volatile("cp.async.commit_group;" ::: "memory")
#define SWZ(b) ((b) ^ (((b) >> 3) & 0x70))

__device__ __forceinline__ uint32_t lds32(uint32_t a) {
    uint32_t v;
    asm volatile("ld.shared.b32 %0, [%1];" : "=r"(v) : "r"(a));
    return v;
}

__device__ __forceinline__ void mma_tf32(float* d, const uint32_t* a, const uint32_t* b) {
    asm volatile(
        "mma.sync.aligned.m16n8k8.row.col.f32.tf32.tf32.f32 "
        "{%0,%1,%2,%3}, {%4,%5,%6,%7}, {%8,%9}, {%0,%1,%2,%3};"
        : "+f"(d[0]), "+f"(d[1]), "+f"(d[2]), "+f"(d[3])
        : "r"(a[0]), "r"(a[1]), "r"(a[2]), "r"(a[3]), "r"(b[0]), "r"(b[1]));
}

// ---------------- packed f32x2 helpers (flash) -----------------------
__device__ __forceinline__ void ffma2(u64 &d, u64 a, u64 b) {
    asm("fma.rn.f32x2 %0, %1, %2, %0;" : "+l"(d) : "l"(a), "l"(b));
}
__device__ __forceinline__ u64 dup2(float x) {
    u64 r; asm("mov.b64 %0, {%1, %1};" : "=l"(r) : "f"(x)); return r;
}
__device__ __forceinline__ u64 pack2(float lo, float hi) {
    u64 r; asm("mov.b64 %0, {%1, %2};" : "=l"(r) : "f"(lo), "f"(hi)); return r;
}
__device__ __forceinline__ void unpack2(u64 v, float &lo, float &hi) {
    asm("mov.b64 {%0, %1}, %2;" : "=f"(lo), "=f"(hi) : "l"(v));
}
__device__ __forceinline__ void mul2(u64 &d, u64 a) {
    asm("mul.rn.f32x2 %0, %0, %1;" : "+l"(d) : "l"(a));
}

// ---------------- weight transpose: out[n,k] = in[k,n] -------------------
__global__ void transpose_kernel(const float* __restrict__ in, float* __restrict__ out,
                                 int K, int N) {
    __shared__ float t[32][33];
    int bn = blockIdx.x << 5, bk = blockIdx.y << 5;
    int tx = threadIdx.x, ty = threadIdx.y;   // 32 x 8
#pragma unroll
    for (int i = 0; i < 4; i++)
        t[ty + i * 8][tx] = in[(size_t)(bk + ty + i * 8) * N + bn + tx];
    __syncthreads();
#pragma unroll
    for (int i = 0; i < 4; i++)
        out[(size_t)(bn + ty + i * 8) * K + bk + tx] = t[tx][ty + i * 8];
}

// ---------------- LayerNorm -------------------------------------------
__global__ void ln_kernel(const float* __restrict__ x, const float* __restrict__ w,
                          const float* __restrict__ b, float* __restrict__ out) {
    int row = blockIdx.x;
    const float* xr = x + (size_t)row * CDIM;
    float* orow = out + (size_t)row * CDIM;
    int t = threadIdx.x;
    float v0 = xr[t], v1 = xr[t + 256], v2 = xr[t + 512];
    float s = v0 + v1 + v2;
    float q = v0 * v0 + v1 * v1 + v2 * v2;
#pragma unroll
    for (int o = 16; o; o >>= 1) {
        s += __shfl_xor_sync(0xffffffffu, s, o);
        q += __shfl_xor_sync(0xffffffffu, q, o);
    }
    __shared__ float rs[8], rq[8];
    if ((t & 31) == 0) { rs[t >> 5] = s; rq[t >> 5] = q; }
    __syncthreads();
    if (t < 32) {
        float us = (t < 8) ? rs[t] : 0.f;
        float uq = (t < 8) ? rq[t] : 0.f;
#pragma unroll
        for (int o = 4; o; o >>= 1) {
            us += __shfl_xor_sync(0xffffffffu, us, o);
            uq += __shfl_xor_sync(0xffffffffu, uq, o);
        }
        if (t == 0) { rs[0] = us; rq[0] = uq; }
    }
    __syncthreads();
    float mu  = rs[0] * (1.f / CDIM);
    float var = rq[0] * (1.f / CDIM) - mu * mu;
    float inv = rsqrtf(var + 1e-5f);
    orow[t]       = (v0 - mu) * inv * w[t]       + b[t];
    orow[t + 256] = (v1 - mu) * inv * w[t + 256] + b[t + 256];
    orow[t + 512] = (v2 - mu) * inv * w[t + 512] + b[t + 512];
}

// ---------------- tf32 mma.sync GEMM: C[M,N] = A[M,K] @ Bt[N,K]^T ---------
// Tile 128x128, BK=32, 8 warps of 64x32, m16n8k8 fragments, SW128 swizzle.
// smem: A buf 16KB + B buf 16KB, double buffered = 64KB dynamic.
__global__ void __launch_bounds__(256)
gemm_mma(const float* __restrict__ A, const float* __restrict__ Bt,
         float* __restrict__ C, int N, int K,
         const float* __restrict__ bias, const float* __restrict__ resid,
         int gelu_flag) {
    extern __shared__ char smem[];
    const uint32_t sb = smem_u32(smem);
    const int tid = threadIdx.x;
    const int wid = tid >> 5, lane = tid & 31;
    const int warp_m = wid & 1, warp_n = wid >> 1;       // 2 x 4 warps
    const int cl = lane & 3;                             // threadID in group
    const int r  = lane >> 2;                            // groupID (0..7)
    const int bn = blockIdx.x << 7, bm = blockIdx.y << 7;

    const int nBK = K >> 5;

    float d[4][4][4];
#pragma unroll
    for (int i = 0; i < 4; i++)
#pragma unroll
        for (int j = 0; j < 4; j++)
#pragma unroll
            for (int e = 0; e < 4; e++) d[i][j][e] = 0.f;

#define LOADT(k0, buf)                                                          \
    {                                                                           \
        uint32_t base = sb + ((buf) ? 32768u : 0u);                             \
        _Pragma("unroll")                                                       \
        for (int i = 0; i < 4; i++) {                                           \
            int id = tid + (i << 8);                                            \
            int row = id >> 3, c4 = id & 7;                                     \
            uint32_t byo = (uint32_t)(row * 128 + (c4 << 4));                   \
            uint32_t dst = base + SWZ(byo);                                     \
            cp_async16(dst, A + (size_t)(bm + row) * K + (k0) + (c4 << 2));     \
            cp_async16(dst + 16384u,                                            \
                       Bt + (size_t)(bn + row) * K + (k0) + (c4 << 2));         \
        }                                                                       \
        CP_COMMIT();                                                            \
    }

    LOADT(0, 0);
    if (nBK > 1) LOADT(32, 1);

    const uint32_t swz16 = (uint32_t)r << 4;
    const uint32_t rowa = (uint32_t)(warp_m * 64 + r) * 128u;
    const uint32_t rowb = (uint32_t)(warp_n * 32 + r) * 128u;

    for (int c = 0; c < nBK; c++) {
        int buf = c & 1;
        if (c == nBK - 1) asm volatile("cp.async.wait_group 0;" ::: "memory");
        else              asm volatile("cp.async.wait_group 1;" ::: "memory");
        __syncthreads();

        const uint32_t Ab = sb + (buf ? 32768u : 0u) + rowa;
        const uint32_t Bb = sb + (buf ? 32768u : 0u) + 16384u + rowb;

#pragma unroll
        for (int ks = 0; ks < 4; ks++) {
            uint32_t k0x = (uint32_t)((ks * 8 + cl) << 2) ^ swz16;
            uint32_t k1x = (uint32_t)((ks * 8 + cl + 4) << 2) ^ swz16;
            uint32_t av[4][4], bv[4][2];
#pragma unroll
            for (int i = 0; i < 4; i++) {
                uint32_t r0 = Ab + (uint32_t)(i * 16 * 128);
                av[i][0] = lds32(r0 + k0x);
                av[i][1] = lds32(r0 + 8 * 128 + k0x);
                av[i][2] = lds32(r0 + k1x);
                av[i][3] = lds32(r0 + 8 * 128 + k1x);
            }
#pragma unroll
            for (int j = 0; j < 4; j++) {
                uint32_t rb = Bb + (uint32_t)(j * 8 * 128);
                bv[j][0] = lds32(rb + k0x);
                bv[j][1] = lds32(rb + k1x);
            }
#pragma unroll
            for (int i = 0; i < 4; i++)
#pragma unroll
                for (int j = 0; j < 4; j++) mma_tf32(d[i][j], av[i], bv[j]);
        }
        __syncthreads();
        if (c + 2 < nBK) LOADT((c + 2) << 5, buf);
    }

    // epilogue
    const int m0w = bm + warp_m * 64 + r;
    const int n0w = bn + warp_n * 32 + cl * 2;
#pragma unroll
    for (int i = 0; i < 4; i++) {
#pragma unroll
        for (int h = 0; h < 2; h++) {
            int row = m0w + i * 16 + h * 8;
            float* Crow = C + (size_t)row * N;
            const float* Rrow = resid ? resid + (size_t)row * N : (const float*)0;
#pragma unroll
            for (int j = 0; j < 4; j++) {
                int col = n0w + j * 8;
                float v0 = d[i][j][h * 2 + 0];
                float v1 = d[i][j][h * 2 + 1];
                if (bias) { v0 += bias[col]; v1 += bias[col + 1]; }
                if (gelu_flag) {
                    v0 = 0.5f * v0 * (1.f + erff(v0 * 0.70710678118654752f));
                    v1 = 0.5f * v1 * (1.f + erff(v1 * 0.70710678118654752f));
                }
                if (Rrow) { v0 += Rrow[col]; v1 += Rrow[col + 1]; }
                *(float2*)&Crow[col] = make_float2(v0, v1);
            }
        }
    }
#undef LOADT
}
#define GEMM_SMEM 65536

// ---------------- fused flash attention (FFMA2) --------------------------
__global__ void __launch_bounds__(256, 1)
flash_kernel(const float* __restrict__ qkv, float* __restrict__ att) {
    extern __shared__ float sm[];
    float* Qs = sm;                    // [64][132]
    float* Ks = Qs + 64 * 132;         // [64][132]
    float* Vs = Ks + 64 * 132;         // [128][68]
    float* Ps = Vs + 128 * 68;         // [128][128] swizzled

    const int tid = threadIdx.x;
    const int tx = tid & 15, ty = tid >> 4;
    const int qb = blockIdx.x << 7;
    const int bh = blockIdx.y;
    const int b = bh / NHEAD, h = bh % NHEAD;
    const float* qptr = qkv + (size_t)b * SEQ * QKVC + h * HDIM;
    const float* kptr = qptr + CDIM;
    const float* vptr = qptr + 2 * CDIM;

#pragma unroll
    for (int c = 0; c < 8; c++) {
        int idx = tid + (c << 8);
        int r = idx >> 4;
        int d4 = (idx & 15) << 2;
        float4 v = *(const float4*)(qptr + (size_t)(qb + r) * QKVC + d4);
        Qs[(d4 + 0) * 132 + r] = v.x * 8.0f;
        Qs[(d4 + 1) * 132 + r] = v.y * 8.0f;
        Qs[(d4 + 2) * 132 + r] = v.z * 8.0f;
        Qs[(d4 + 3) * 132 + r] = v.w * 8.0f;
    }

    float m_i[8], l_i[8];
#pragma unroll
    for (int i = 0; i < 8; i++) { m_i[i] = -3.4e38f; l_i[i] = 0.f; }
    u64 Oa[4][4];
#pragma unroll
    for (int p = 0; p < 4; p++)
#pragma unroll
        for (int e = 0; e < 4; e++) Oa[p][e] = 0ULL;

    const int sw = tx & 7;

    for (int n0 = 0; n0 < SEQ; n0 += 128) {
        __syncthreads();
#pragma unroll
        for (int c = 0; c < 8; c++) {
            int idx = tid + (c << 8);
            int r = idx >> 4;
            int d4 = (idx & 15) << 2;
            float4 kv = *(const float4*)(kptr + (size_t)(n0 + r) * QKVC + d4);
            Ks[(d4 + 0) * 132 + r] = kv.x;
            Ks[(d4 + 1) * 132 + r] = kv.y;
            Ks[(d4 + 2) * 132 + r] = kv.z;
            Ks[(d4 + 3) * 132 + r] = kv.w;
            float4 vv = *(const float4*)(vptr + (size_t)(n0 + r) * QKVC + d4);
            *(float4*)&Vs[r * 68 + d4] = vv;
        }
        __syncthreads();

        u64 sacc[8][4];
#pragma unroll
        for (int i = 0; i < 8; i++)
#pragma unroll
            for (int j = 0; j < 4; j++) sacc[i][j] = 0ULL;
#pragma unroll 8
        for (int kk = 0; kk < 64; kk++) {
            float4 a0 = *(const float4*)&Qs[kk * 132 + (ty << 3)];
            float4 a1 = *(const float4*)&Qs[kk * 132 + (ty << 3) + 4];
            ulonglong2 b0 = *(const ulonglong2*)&Ks[kk * 132 + (tx << 3)];
            ulonglong2 b1 = *(const ulonglong2*)&Ks[kk * 132 + (tx << 3) + 4];
            u64 ad[8] = {dup2(a0.x), dup2(a0.y), dup2(a0.z), dup2(a0.w),
                         dup2(a1.x), dup2(a1.y), dup2(a1.z), dup2(a1.w)};
            u64 bb[4] = {b0.x, b0.y, b1.x, b1.y};
#pragma unroll
            for (int i = 0; i < 8; i++)
#pragma unroll
                for (int j = 0; j < 4; j++) ffma2(sacc[i][j], ad[i], bb[j]);
        }

        float p[8][8];
#pragma unroll
        for (int i = 0; i < 8; i++)
#pragma unroll
            for (int jp = 0; jp < 4; jp++)
                unpack2(sacc[i][jp], p[i][2 * jp], p[i][2 * jp + 1]);

        float c8[8];
#pragma unroll
        for (int i = 0; i < 8; i++) {
            float mx = p[i][0];
#pragma unroll
            for (int j = 1; j < 8; j++) mx = fmaxf(mx, p[i][j]);
#pragma unroll
            for (int o = 8; o; o >>= 1) mx = fmaxf(mx, __shfl_xor_sync(0xffffffffu, mx, o));
            float mnew = fmaxf(m_i[i], mx);
            c8[i] = __expf(m_i[i] - mnew);
            m_i[i] = mnew;
            float rs = 0.f;
#pragma unroll
            for (int j = 0; j < 8; j++) { p[i][j] = __expf(p[i][j] - mnew); rs += p[i][j]; }
#pragma unroll
            for (int o = 8; o; o >>= 1) rs += __shfl_xor_sync(0xffffffffu, rs, o);
            l_i[i] = l_i[i] * c8[i] + rs;
        }
#pragma unroll
        for (int p2 = 0; p2 < 4; p2++) {
            u64 cp = pack2(c8[2 * p2], c8[2 * p2 + 1]);
#pragma unroll
            for (int e = 0; e < 4; e++) mul2(Oa[p2][e], cp);
        }

#pragma unroll
        for (int jj = 0; jj < 8; jj++) {
            float* prow = Ps + ((tx << 3) + jj) * 128;
            *(float4*)&prow[(((ty << 1) + 0) ^ sw) << 2] =
                make_float4(p[0][jj], p[1][jj], p[2][jj], p[3][jj]);
            *(float4*)&prow[(((ty << 1) + 1) ^ sw) << 2] =
                make_float4(p[4][jj], p[5][jj], p[6][jj], p[7][jj]);
        }
        __syncthreads();

#pragma unroll 8
        for (int kk = 0; kk < 128; kk++) {
            int swk = (kk >> 3) & 7;
            const float* prow = Ps + kk * 128;
            ulonglong2 ap0 = *(const ulonglong2*)&prow[(((ty << 1) + 0) ^ swk) << 2];
            ulonglong2 ap1 = *(const ulonglong2*)&prow[(((ty << 1) + 1) ^ swk) << 2];
            float4 vf = *(const float4*)&Vs[kk * 68 + (tx << 2)];
            u64 vd[4] = {dup2(vf.x), dup2(vf.y), dup2(vf.z), dup2(vf.w)};
            u64 aa[4] = {ap0.x, ap0.y, ap1.x, ap1.y};
#pragma unroll
            for (int p2 = 0; p2 < 4; p2++)
#pragma unroll
                for (int e = 0; e < 4; e++) ffma2(Oa[p2][e], aa[p2], vd[e]);
        }
    }

#pragma unroll
    for (int p2 = 0; p2 < 4; p2++) {
        int i0 = (ty << 3) + 2 * p2;
        float inv0 = 1.f / l_i[2 * p2];
        float inv1 = 1.f / l_i[2 * p2 + 1];
        float* o0 = att + ((size_t)(b * SEQ + qb + i0)) * CDIM + h * HDIM + (tx << 2);
        float* o1 = o0 + CDIM;
        float v0[4], v1[4];
#pragma unroll
        for (int e = 0; e < 4; e++) {
            float lo, hi;
            unpack2(Oa[p2][e], lo, hi);
            v0[e] = lo * inv0;
            v1[e] = hi * inv1;
        }
        *(float4*)o0 = make_float4(v0[0], v0[1], v0[2], v0[3]);
        *(float4*)o1 = make_float4(v1[0], v1[1], v1[2], v1[3]);
    }
}

// ---------------- launch --------------------------------------------------
extern "C" void kernel_launch(void* const* d_in, const int* in_sizes, int n_in,
                              void* d_out, int out_size) {
    const float* x     = (const float*)d_in[0];
    const float* ln1w  = (const float*)d_in[1];
    const float* ln1b  = (const float*)d_in[2];
    const float* ln2w  = (const float*)d_in[3];
    const float* ln2b  = (const float*)d_in[4];
    const float* wqkv  = (const float*)d_in[5];
    const float* wproj = (const float*)d_in[6];
    const float* wfc1  = (const float*)d_in[7];
    const float* bfc1  = (const float*)d_in[8];
    const float* wfc2  = (const float*)d_in[9];
    const float* bfc2  = (const float*)d_in[10];
    float* out = (float*)d_out;

    float *p_h, *p_qkv, *p_att, *p_x1, *p_fc1;
    float *p_wqkv_t, *p_wproj_t, *p_wfc1_t, *p_wfc2_t;
    cudaGetSymbolAddress((void**)&p_h, g_h);
    cudaGetSymbolAddress((void**)&p_qkv, g_qkv);
    cudaGetSymbolAddress((void**)&p_att, g_att);
    cudaGetSymbolAddress((void**)&p_x1, g_x1);
    cudaGetSymbolAddress((void**)&p_fc1, g_fc1);
    cudaGetSymbolAddress((void**)&p_wqkv_t, g_wqkv_t);
    cudaGetSymbolAddress((void**)&p_wproj_t, g_wproj_t);
    cudaGetSymbolAddress((void**)&p_wfc1_t, g_wfc1_t);
    cudaGetSymbolAddress((void**)&p_wfc2_t, g_wfc2_t);

    static const int FLASH_SMEM = (64 * 132 + 64 * 132 + 128 * 68 + 128 * 128) * 4;
    cudaFuncSetAttribute(flash_kernel, cudaFuncAttributeMaxDynamicSharedMemorySize,
                         FLASH_SMEM);
    cudaFuncSetAttribute(gemm_mma, cudaFuncAttributeMaxDynamicSharedMemorySize,
                         GEMM_SMEM);

    dim3 tb(32, 8);
    transpose_kernel<<<dim3(QKVC / 32, CDIM / 32), tb>>>(wqkv, p_wqkv_t, CDIM, QKVC);
    transpose_kernel<<<dim3(CDIM / 32, CDIM / 32), tb>>>(wproj, p_wproj_t, CDIM, CDIM);
    transpose_kernel<<<dim3(HID / 32, CDIM / 32), tb>>>(wfc1, p_wfc1_t, CDIM, HID);
    transpose_kernel<<<dim3(CDIM / 32, HID / 32), tb>>>(wfc2, p_wfc2_t, HID, CDIM);

    // 1) h = LN1(x)
    ln_kernel<<<TOKS, 256>>>(x, ln1w, ln1b, p_h);
    // 2) qkv = h @ w_qkv
    gemm_mma<<<dim3(QKVC / 128, TOKS / 128), 256, GEMM_SMEM>>>(
        p_h, p_wqkv_t, p_qkv, QKVC, CDIM, nullptr, nullptr, 0);
    // 3-5) fused attention
    flash_kernel<<<dim3(SEQ / 128, NBH), 256, FLASH_SMEM>>>(p_qkv, p_att);
    // 6) x1 = x + att @ w_proj
    gemm_mma<<<dim3(CDIM / 128, TOKS / 128), 256, GEMM_SMEM>>>(
        p_att, p_wproj_t, p_x1, CDIM, CDIM, nullptr, x, 0);
    // 7) h = LN2(x1)
    ln_kernel<<<TOKS, 256>>>(p_x1, ln2w, ln2b, p_h);
    // 8) fc1 = gelu(h @ w_fc1 + b_fc1)
    gemm_mma<<<dim3(HID / 128, TOKS / 128), 256, GEMM_SMEM>>>(
        p_h, p_wfc1_t, p_fc1, HID, CDIM, bfc1, nullptr, 1);
    // 9) out = x1 + fc1 @ w_fc2 + b_fc2
    gemm_mma<<<dim3(CDIM / 128, TOKS / 128), 256, GEMM_SMEM>>>(
        p_fc1, p_wfc2_t, out, CDIM, HID, bfc2, p_x1, 0);
}

// round 5
// speedup vs baseline: 3.1647x; 1.3079x over previous
#include <cuda_runtime.h>
#include <math.h>
#include <stddef.h>
#include <stdint.h>

// ---------------- problem constants ----------------
#define TOKS   8192
#define CDIM   768
#define HID    384
#define NHEAD  12
#define HDIM   64
#define SEQ    1024
#define QKVC   2304
#define NBH    96

// ---------------- scratch ---------------------------
__device__ float g_h[(size_t)TOKS * CDIM];
__device__ float g_qkv[(size_t)TOKS * QKVC];
__device__ float g_att[(size_t)TOKS * CDIM];
__device__ float g_x1[(size_t)TOKS * CDIM];
__device__ float g_fc1[(size_t)TOKS * HID];
__device__ float g_wqkv_t[(size_t)QKVC * CDIM];
__device__ float g_wproj_t[(size_t)CDIM * CDIM];
__device__ float g_wfc1_t[(size_t)HID * CDIM];
__device__ float g_wfc2_t[(size_t)CDIM * HID];

typedef unsigned long long u64;

// ---------------- helpers -----------------------
__device__ __forceinline__ uint32_t smem_u32(const void* p) {
    uint32_t a;
    asm("{ .reg .u64 t; cvta.to.shared.u64 t, %1; cvt.u32.u64 %0, t; }" : "=r"(a) : "l"(p));
    return a;
}
__device__ __forceinline__ void cp_async16(uint32_t dst, const void* src) {
    asm volatile("cp.async.cg.shared.global [%0], [%1], 16;" :: "r"(dst), "l"(src));
}
#define CP_COMMIT() asm volatile("cp.async.commit_group;" ::: "memory")
#define SWZ(b) ((b) ^ (((b) >> 3) & 0x70))

__device__ __forceinline__ uint32_t lds32(uint32_t a) {
    uint32_t v;
    asm volatile("ld.shared.b32 %0, [%1];" : "=r"(v) : "r"(a));
    return v;
}

__device__ __forceinline__ void mma_tf32(float* d, const uint32_t* a, const uint32_t* b) {
    asm volatile(
        "mma.sync.aligned.m16n8k8.row.col.f32.tf32.tf32.f32 "
        "{%0,%1,%2,%3}, {%4,%5,%6,%7}, {%8,%9}, {%0,%1,%2,%3};"
        : "+f"(d[0]), "+f"(d[1]), "+f"(d[2]), "+f"(d[3])
        : "r"(a[0]), "r"(a[1]), "r"(a[2]), "r"(a[3]), "r"(b[0]), "r"(b[1]));
}

__device__ __forceinline__ float cvt_tf32(float x) {
    uint32_t u;
    asm("cvt.rna.tf32.f32 %0, %1;" : "=r"(u) : "f"(x));
    return __uint_as_float(u);
}

// ---------------- weight transpose: out[n,k] = in[k,n] -------------------
__global__ void transpose_kernel(const float* __restrict__ in, float* __restrict__ out,
                                 int K, int N) {
    __shared__ float t[32][33];
    int bn = blockIdx.x << 5, bk = blockIdx.y << 5;
    int tx = threadIdx.x, ty = threadIdx.y;   // 32 x 8
#pragma unroll
    for (int i = 0; i < 4; i++)
        t[ty + i * 8][tx] = in[(size_t)(bk + ty + i * 8) * N + bn + tx];
    __syncthreads();
#pragma unroll
    for (int i = 0; i < 4; i++)
        out[(size_t)(bn + ty + i * 8) * K + bk + tx] = t[tx][ty + i * 8];
}

// ---------------- LayerNorm -------------------------------------------
__global__ void ln_kernel(const float* __restrict__ x, const float* __restrict__ w,
                          const float* __restrict__ b, float* __restrict__ out) {
    int row = blockIdx.x;
    const float* xr = x + (size_t)row * CDIM;
    float* orow = out + (size_t)row * CDIM;
    int t = threadIdx.x;
    float v0 = xr[t], v1 = xr[t + 256], v2 = xr[t + 512];
    float s = v0 + v1 + v2;
    float q = v0 * v0 + v1 * v1 + v2 * v2;
#pragma unroll
    for (int o = 16; o; o >>= 1) {
        s += __shfl_xor_sync(0xffffffffu, s, o);
        q += __shfl_xor_sync(0xffffffffu, q, o);
    }
    __shared__ float rs[8], rq[8];
    if ((t & 31) == 0) { rs[t >> 5] = s; rq[t >> 5] = q; }
    __syncthreads();
    if (t < 32) {
        float us = (t < 8) ? rs[t] : 0.f;
        float uq = (t < 8) ? rq[t] : 0.f;
#pragma unroll
        for (int o = 4; o; o >>= 1) {
            us += __shfl_xor_sync(0xffffffffu, us, o);
            uq += __shfl_xor_sync(0xffffffffu, uq, o);
        }
        if (t == 0) { rs[0] = us; rq[0] = uq; }
    }
    __syncthreads();
    float mu  = rs[0] * (1.f / CDIM);
    float var = rq[0] * (1.f / CDIM) - mu * mu;
    float inv = rsqrtf(var + 1e-5f);
    orow[t]       = (v0 - mu) * inv * w[t]       + b[t];
    orow[t + 256] = (v1 - mu) * inv * w[t + 256] + b[t + 256];
    orow[t + 512] = (v2 - mu) * inv * w[t + 512] + b[t + 512];
}

// ---------------- tf32 mma.sync GEMM (from R4, unchanged) ----------------
__global__ void __launch_bounds__(256)
gemm_mma(const float* __restrict__ A, const float* __restrict__ Bt,
         float* __restrict__ C, int N, int K,
         const float* __restrict__ bias, const float* __restrict__ resid,
         int gelu_flag) {
    extern __shared__ char smem[];
    const uint32_t sb = smem_u32(smem);
    const int tid = threadIdx.x;
    const int wid = tid >> 5, lane = tid & 31;
    const int warp_m = wid & 1, warp_n = wid >> 1;
    const int cl = lane & 3;
    const int r  = lane >> 2;
    const int bn = blockIdx.x << 7, bm = blockIdx.y << 7;

    const int nBK = K >> 5;

    float d[4][4][4];
#pragma unroll
    for (int i = 0; i < 4; i++)
#pragma unroll
        for (int j = 0; j < 4; j++)
#pragma unroll
            for (int e = 0; e < 4; e++) d[i][j][e] = 0.f;

#define LOADT(k0, buf)                                                          \
    {                                                                           \
        uint32_t base = sb + ((buf) ? 32768u : 0u);                             \
        _Pragma("unroll")                                                       \
        for (int i = 0; i < 4; i++) {                                           \
            int id = tid + (i << 8);                                            \
            int row = id >> 3, c4 = id & 7;                                     \
            uint32_t byo = (uint32_t)(row * 128 + (c4 << 4));                   \
            uint32_t dst = base + SWZ(byo);                                     \
            cp_async16(dst, A + (size_t)(bm + row) * K + (k0) + (c4 << 2));     \
            cp_async16(dst + 16384u,                                            \
                       Bt + (size_t)(bn + row) * K + (k0) + (c4 << 2));         \
        }                                                                       \
        CP_COMMIT();                                                            \
    }

    LOADT(0, 0);
    if (nBK > 1) LOADT(32, 1);

    const uint32_t swz16 = (uint32_t)r << 4;
    const uint32_t rowa = (uint32_t)(warp_m * 64 + r) * 128u;
    const uint32_t rowb = (uint32_t)(warp_n * 32 + r) * 128u;

    for (int c = 0; c < nBK; c++) {
        int buf = c & 1;
        if (c == nBK - 1) asm volatile("cp.async.wait_group 0;" ::: "memory");
        else              asm volatile("cp.async.wait_group 1;" ::: "memory");
        __syncthreads();

        const uint32_t Ab = sb + (buf ? 32768u : 0u) + rowa;
        const uint32_t Bb = sb + (buf ? 32768u : 0u) + 16384u + rowb;

#pragma unroll
        for (int ks = 0; ks < 4; ks++) {
            uint32_t k0x = (uint32_t)((ks * 8 + cl) << 2) ^ swz16;
            uint32_t k1x = (uint32_t)((ks * 8 + cl + 4) << 2) ^ swz16;
            uint32_t av[4][4], bv[4][2];
#pragma unroll
            for (int i = 0; i < 4; i++) {
                uint32_t r0 = Ab + (uint32_t)(i * 16 * 128);
                av[i][0] = lds32(r0 + k0x);
                av[i][1] = lds32(r0 + 8 * 128 + k0x);
                av[i][2] = lds32(r0 + k1x);
                av[i][3] = lds32(r0 + 8 * 128 + k1x);
            }
#pragma unroll
            for (int j = 0; j < 4; j++) {
                uint32_t rb = Bb + (uint32_t)(j * 8 * 128);
                bv[j][0] = lds32(rb + k0x);
                bv[j][1] = lds32(rb + k1x);
            }
#pragma unroll
            for (int i = 0; i < 4; i++)
#pragma unroll
                for (int j = 0; j < 4; j++) mma_tf32(d[i][j], av[i], bv[j]);
        }
        __syncthreads();
        if (c + 2 < nBK) LOADT((c + 2) << 5, buf);
    }

    const int m0w = bm + warp_m * 64 + r;
    const int n0w = bn + warp_n * 32 + cl * 2;
#pragma unroll
    for (int i = 0; i < 4; i++) {
#pragma unroll
        for (int h = 0; h < 2; h++) {
            int row = m0w + i * 16 + h * 8;
            float* Crow = C + (size_t)row * N;
            const float* Rrow = resid ? resid + (size_t)row * N : (const float*)0;
#pragma unroll
            for (int j = 0; j < 4; j++) {
                int col = n0w + j * 8;
                float v0 = d[i][j][h * 2 + 0];
                float v1 = d[i][j][h * 2 + 1];
                if (bias) { v0 += bias[col]; v1 += bias[col + 1]; }
                if (gelu_flag) {
                    v0 = 0.5f * v0 * (1.f + erff(v0 * 0.70710678118654752f));
                    v1 = 0.5f * v1 * (1.f + erff(v1 * 0.70710678118654752f));
                }
                if (Rrow) { v0 += Rrow[col]; v1 += Rrow[col + 1]; }
                *(float2*)&Crow[col] = make_float2(v0, v1);
            }
        }
    }
#undef LOADT
}
#define GEMM_SMEM 65536

// ---------------- flash attention, tensor-core version --------------------
// CTA: 128 q-rows of one (b,h); kv tiles of 64; 8 warps x 16 q-rows.
// QK^T in 3xTF32 (near-fp32 logits), PV in single tf32.
// All smem tiles stride 68 floats (68 % 32 == 4) -> fragment loads at
// bank (4r+cl) are conflict-free.
#define FD 68

__global__ void __launch_bounds__(256, 1)
flash_mma(const float* __restrict__ qkv, float* __restrict__ att) {
    extern __shared__ float sm[];
    float* Qhi = sm;                     // [128][FD]
    float* Qlo = Qhi + 128 * FD;         // [128][FD]
    float* Khi = Qlo + 128 * FD;         // [64][FD]
    float* Klo = Khi + 64 * FD;          // [64][FD]
    float* Vt  = Klo + 64 * FD;          // [64][FD]  (Vt[d][kv])
    float* Ps  = Vt + 64 * FD;           // [128][FD]

    const int tid = threadIdx.x;
    const int wid = tid >> 5, lane = tid & 31;
    const int r = lane >> 2, cl = lane & 3;
    const int qb = blockIdx.x << 7;
    const int bh = blockIdx.y;
    const int b = bh / NHEAD, h = bh % NHEAD;
    const float* qptr = qkv + (size_t)b * SEQ * QKVC + h * HDIM;
    const float* kptr = qptr + CDIM;
    const float* vptr = qptr + 2 * CDIM;

    // ---- load Q (x8 scale folded), split hi/lo ----
    {
        int row = tid >> 1;
        const float* src = qptr + (size_t)(qb + row) * QKVC;
#pragma unroll
        for (int e = 0; e < 8; e++) {
            int c4 = ((tid & 1) << 3) + e;
            float4 v = *(const float4*)(src + (c4 << 2));
            v.x *= 8.f; v.y *= 8.f; v.z *= 8.f; v.w *= 8.f;
            float4 hi, lo;
            hi.x = cvt_tf32(v.x); lo.x = v.x - hi.x;
            hi.y = cvt_tf32(v.y); lo.y = v.y - hi.y;
            hi.z = cvt_tf32(v.z); lo.z = v.z - hi.z;
            hi.w = cvt_tf32(v.w); lo.w = v.w - hi.w;
            *(float4*)&Qhi[row * FD + (c4 << 2)] = hi;
            *(float4*)&Qlo[row * FD + (c4 << 2)] = lo;
        }
    }

    float mi0 = -3.4e38f, mi1 = -3.4e38f, li0 = 0.f, li1 = 0.f;
    float o[8][4];
#pragma unroll
    for (int j = 0; j < 8; j++)
#pragma unroll
        for (int e = 0; e < 4; e++) o[j][e] = 0.f;

    const int m0 = wid << 4;

    for (int t = 0; t < 16; t++) {
        __syncthreads();   // prior PV done reading Vt/Ps before overwrite
        // ---- load K (split hi/lo) and V (transposed) ----
        {
            int row = tid >> 2;
            const float* ksrc = kptr + (size_t)((t << 6) + row) * QKVC;
            const float* vsrc = vptr + (size_t)((t << 6) + row) * QKVC;
#pragma unroll
            for (int e = 0; e < 4; e++) {
                int c4 = (tid & 3) + (e << 2);
                float4 v = *(const float4*)(ksrc + (c4 << 2));
                float4 hi, lo;
                hi.x = cvt_tf32(v.x); lo.x = v.x - hi.x;
                hi.y = cvt_tf32(v.y); lo.y = v.y - hi.y;
                hi.z = cvt_tf32(v.z); lo.z = v.z - hi.z;
                hi.w = cvt_tf32(v.w); lo.w = v.w - hi.w;
                *(float4*)&Khi[row * FD + (c4 << 2)] = hi;
                *(float4*)&Klo[row * FD + (c4 << 2)] = lo;
                float4 vv = *(const float4*)(vsrc + (c4 << 2));
                int dc = c4 << 2;
                Vt[(dc + 0) * FD + row] = vv.x;
                Vt[(dc + 1) * FD + row] = vv.y;
                Vt[(dc + 2) * FD + row] = vv.z;
                Vt[(dc + 3) * FD + row] = vv.w;
            }
        }
        __syncthreads();

        // ---- S = Q K^T (3xTF32): warp covers 16 q-rows x 64 kv ----
        float s[8][4];
#pragma unroll
        for (int j = 0; j < 8; j++)
#pragma unroll
            for (int e = 0; e < 4; e++) s[j][e] = 0.f;

#pragma unroll
        for (int ks = 0; ks < 8; ks++) {
            int k0 = ks << 3;
            uint32_t ah[4], al[4];
            ah[0] = __float_as_uint(Qhi[(m0 + r) * FD + k0 + cl]);
            ah[1] = __float_as_uint(Qhi[(m0 + r + 8) * FD + k0 + cl]);
            ah[2] = __float_as_uint(Qhi[(m0 + r) * FD + k0 + cl + 4]);
            ah[3] = __float_as_uint(Qhi[(m0 + r + 8) * FD + k0 + cl + 4]);
            al[0] = __float_as_uint(Qlo[(m0 + r) * FD + k0 + cl]);
            al[1] = __float_as_uint(Qlo[(m0 + r + 8) * FD + k0 + cl]);
            al[2] = __float_as_uint(Qlo[(m0 + r) * FD + k0 + cl + 4]);
            al[3] = __float_as_uint(Qlo[(m0 + r + 8) * FD + k0 + cl + 4]);
#pragma unroll
            for (int j = 0; j < 8; j++) {
                int nr = (j << 3) + r;
                uint32_t bh2[2], bl2[2];
                bh2[0] = __float_as_uint(Khi[nr * FD + k0 + cl]);
                bh2[1] = __float_as_uint(Khi[nr * FD + k0 + cl + 4]);
                bl2[0] = __float_as_uint(Klo[nr * FD + k0 + cl]);
                bl2[1] = __float_as_uint(Klo[nr * FD + k0 + cl + 4]);
                mma_tf32(s[j], ah, bh2);
                mma_tf32(s[j], al, bh2);
                mma_tf32(s[j], ah, bl2);
            }
        }

        // ---- online softmax (rows m0+r and m0+r+8) ----
        float mx0 = s[0][0], mx1 = s[0][2];
#pragma unroll
        for (int j = 0; j < 8; j++) {
            mx0 = fmaxf(mx0, fmaxf(s[j][0], s[j][1]));
            mx1 = fmaxf(mx1, fmaxf(s[j][2], s[j][3]));
        }
        mx0 = fmaxf(mx0, __shfl_xor_sync(0xffffffffu, mx0, 1));
        mx0 = fmaxf(mx0, __shfl_xor_sync(0xffffffffu, mx0, 2));
        mx1 = fmaxf(mx1, __shfl_xor_sync(0xffffffffu, mx1, 1));
        mx1 = fmaxf(mx1, __shfl_xor_sync(0xffffffffu, mx1, 2));
        float mn0 = fmaxf(mi0, mx0), mn1 = fmaxf(mi1, mx1);
        float sc0 = __expf(mi0 - mn0), sc1 = __expf(mi1 - mn1);
        mi0 = mn0; mi1 = mn1;
        float sum0 = 0.f, sum1 = 0.f;
#pragma unroll
        for (int j = 0; j < 8; j++) {
            s[j][0] = __expf(s[j][0] - mn0);
            s[j][1] = __expf(s[j][1] - mn0);
            s[j][2] = __expf(s[j][2] - mn1);
            s[j][3] = __expf(s[j][3] - mn1);
            sum0 += s[j][0] + s[j][1];
            sum1 += s[j][2] + s[j][3];
        }
        sum0 += __shfl_xor_sync(0xffffffffu, sum0, 1);
        sum0 += __shfl_xor_sync(0xffffffffu, sum0, 2);
        sum1 += __shfl_xor_sync(0xffffffffu, sum1, 1);
        sum1 += __shfl_xor_sync(0xffffffffu, sum1, 2);
        li0 = li0 * sc0 + sum0;
        li1 = li1 * sc1 + sum1;
#pragma unroll
        for (int j = 0; j < 8; j++) {
            o[j][0] *= sc0; o[j][1] *= sc0;
            o[j][2] *= sc1; o[j][3] *= sc1;
        }

        // ---- store P (per-warp-private rows), relayout D->A via smem ----
#pragma unroll
        for (int j = 0; j < 8; j++) {
            *(float2*)&Ps[(m0 + r) * FD + (j << 3) + (cl << 1)] =
                make_float2(s[j][0], s[j][1]);
            *(float2*)&Ps[(m0 + r + 8) * FD + (j << 3) + (cl << 1)] =
                make_float2(s[j][2], s[j][3]);
        }
        __syncwarp();

        // ---- O += P @ V ----
#pragma unroll
        for (int ks = 0; ks < 8; ks++) {
            int k0 = ks << 3;
            uint32_t a[4];
            a[0] = __float_as_uint(Ps[(m0 + r) * FD + k0 + cl]);
            a[1] = __float_as_uint(Ps[(m0 + r + 8) * FD + k0 + cl]);
            a[2] = __float_as_uint(Ps[(m0 + r) * FD + k0 + cl + 4]);
            a[3] = __float_as_uint(Ps[(m0 + r + 8) * FD + k0 + cl + 4]);
#pragma unroll
            for (int j = 0; j < 8; j++) {
                uint32_t b2[2];
                b2[0] = __float_as_uint(Vt[((j << 3) + r) * FD + k0 + cl]);
                b2[1] = __float_as_uint(Vt[((j << 3) + r) * FD + k0 + cl + 4]);
                mma_tf32(o[j], a, b2);
            }
        }
    }

    // ---- epilogue: O / l -> att in [B,N,C] ----
    {
        float inv0 = 1.f / li0, inv1 = 1.f / li1;
        float* o0 = att + ((size_t)(b * SEQ + qb + m0 + r)) * CDIM + h * HDIM;
        float* o1 = o0 + 8 * CDIM;
#pragma unroll
        for (int j = 0; j < 8; j++) {
            int col = (j << 3) + (cl << 1);
            *(float2*)&o0[col] = make_float2(o[j][0] * inv0, o[j][1] * inv0);
            *(float2*)&o1[col] = make_float2(o[j][2] * inv1, o[j][3] * inv1);
        }
    }
}
#define FLASH_SMEM ((128 + 128 + 64 + 64 + 64 + 128) * FD * 4)

// ---------------- launch --------------------------------------------------
extern "C" void kernel_launch(void* const* d_in, const int* in_sizes, int n_in,
                              void* d_out, int out_size) {
    const float* x     = (const float*)d_in[0];
    const float* ln1w  = (const float*)d_in[1];
    const float* ln1b  = (const float*)d_in[2];
    const float* ln2w  = (const float*)d_in[3];
    const float* ln2b  = (const float*)d_in[4];
    const float* wqkv  = (const float*)d_in[5];
    const float* wproj = (const float*)d_in[6];
    const float* wfc1  = (const float*)d_in[7];
    const float* bfc1  = (const float*)d_in[8];
    const float* wfc2  = (const float*)d_in[9];
    const float* bfc2  = (const float*)d_in[10];
    float* out = (float*)d_out;

    float *p_h, *p_qkv, *p_att, *p_x1, *p_fc1;
    float *p_wqkv_t, *p_wproj_t, *p_wfc1_t, *p_wfc2_t;
    cudaGetSymbolAddress((void**)&p_h, g_h);
    cudaGetSymbolAddress((void**)&p_qkv, g_qkv);
    cudaGetSymbolAddress((void**)&p_att, g_att);
    cudaGetSymbolAddress((void**)&p_x1, g_x1);
    cudaGetSymbolAddress((void**)&p_fc1, g_fc1);
    cudaGetSymbolAddress((void**)&p_wqkv_t, g_wqkv_t);
    cudaGetSymbolAddress((void**)&p_wproj_t, g_wproj_t);
    cudaGetSymbolAddress((void**)&p_wfc1_t, g_wfc1_t);
    cudaGetSymbolAddress((void**)&p_wfc2_t, g_wfc2_t);

    cudaFuncSetAttribute(flash_mma, cudaFuncAttributeMaxDynamicSharedMemorySize,
                         FLASH_SMEM);
    cudaFuncSetAttribute(gemm_mma, cudaFuncAttributeMaxDynamicSharedMemorySize,
                         GEMM_SMEM);

    dim3 tb(32, 8);
    transpose_kernel<<<dim3(QKVC / 32, CDIM / 32), tb>>>(wqkv, p_wqkv_t, CDIM, QKVC);
    transpose_kernel<<<dim3(CDIM / 32, CDIM / 32), tb>>>(wproj, p_wproj_t, CDIM, CDIM);
    transpose_kernel<<<dim3(HID / 32, CDIM / 32), tb>>>(wfc1, p_wfc1_t, CDIM, HID);
    transpose_kernel<<<dim3(CDIM / 32, HID / 32), tb>>>(wfc2, p_wfc2_t, HID, CDIM);

    // 1) h = LN1(x)
    ln_kernel<<<TOKS, 256>>>(x, ln1w, ln1b, p_h);
    // 2) qkv = h @ w_qkv
    gemm_mma<<<dim3(QKVC / 128, TOKS / 128), 256, GEMM_SMEM>>>(
        p_h, p_wqkv_t, p_qkv, QKVC, CDIM, nullptr, nullptr, 0);
    // 3-5) fused attention (tensor cores)
    flash_mma<<<dim3(SEQ / 128, NBH), 256, FLASH_SMEM>>>(p_qkv, p_att);
    // 6) x1 = x + att @ w_proj
    gemm_mma<<<dim3(CDIM / 128, TOKS / 128), 256, GEMM_SMEM>>>(
        p_att, p_wproj_t, p_x1, CDIM, CDIM, nullptr, x, 0);
    // 7) h = LN2(x1)
    ln_kernel<<<TOKS, 256>>>(p_x1, ln2w, ln2b, p_h);
    // 8) fc1 = gelu(h @ w_fc1 + b_fc1)
    gemm_mma<<<dim3(HID / 128, TOKS / 128), 256, GEMM_SMEM>>>(
        p_h, p_wfc1_t, p_fc1, HID, CDIM, bfc1, nullptr, 1);
    // 9) out = x1 + fc1 @ w_fc2 + b_fc2
    gemm_mma<<<dim3(CDIM / 128, TOKS / 128), 256, GEMM_SMEM>>>(
        p_fc1, p_wfc2_t, out, CDIM, HID, bfc2, p_x1, 0);
}